// round 1
// baseline (speedup 1.0000x reference)
#include <cuda_runtime.h>
#include <math.h>

#define BATCH 4
#define NPTS  4096
#define KNN   20
#define CATC  512
#define EPSBN 1e-5f

#define TI 64
#define TJ 64
#define KT 16
#define PAD 68  // 68*4 bytes keeps 16B alignment for float4 smem reads

// ---------------- scratch (static device globals; no allocations) ----------
__device__ float g_dist[(size_t)BATCH * NPTS * NPTS];   // 256 MB
__device__ int   g_idx [(size_t)BATCH * NPTS * KNN];
__device__ float g_xx  [BATCH * NPTS];
__device__ float g_cat [(size_t)BATCH * NPTS * CATC];   // 32 MB (concat of block outputs)
__device__ float g_U   [(size_t)BATCH * NPTS * 256];
__device__ float g_V   [(size_t)BATCH * NPTS * 256];
__device__ float g_Wc  [256 * 128];
__device__ float g_Zp  [BATCH * 512 * 4];

// ---------------- row squared norms --------------------------------------
__global__ void xx_kernel(const float* __restrict__ X, int ldx, int C,
                          float* __restrict__ xx) {
    int r = blockIdx.x * blockDim.x + threadIdx.x;
    if (r >= BATCH * NPTS) return;
    const float* row = X + (size_t)r * ldx;
    float s = 0.f;
    for (int c = 0; c < C; c++) { float v = row[c]; s += v * v; }
    xx[r] = s;
}

// ---------------- Gram / neg-dist GEMM  (per batch, X @ X^T) --------------
__global__ __launch_bounds__(256)
void gram_kernel(const float* __restrict__ X, int ldx, int C,
                 const float* __restrict__ xx, float* __restrict__ dist) {
    __shared__ float As[KT][PAD];
    __shared__ float Bs[KT][PAD];
    int b = blockIdx.z;
    const float* Xb  = X    + (size_t)b * NPTS * ldx;
    const float* xxb = xx   + (size_t)b * NPTS;
    float*       Db  = dist + (size_t)b * NPTS * NPTS;
    int i0 = blockIdx.x * TI, j0 = blockIdx.y * TJ;
    int tid = threadIdx.x;
    int tx = tid & 15, ty = tid >> 4;

    float acc[4][4];
#pragma unroll
    for (int ii = 0; ii < 4; ii++)
#pragma unroll
        for (int jj = 0; jj < 4; jj++) acc[ii][jj] = 0.f;

    for (int k0 = 0; k0 < C; k0 += KT) {
        for (int t = tid; t < TI * KT; t += 256) {
            int r = t >> 4, kk = t & 15;
            float av = 0.f, bv = 0.f;
            if (k0 + kk < C) {
                av = Xb[(size_t)(i0 + r) * ldx + k0 + kk];
                bv = Xb[(size_t)(j0 + r) * ldx + k0 + kk];
            }
            As[kk][r] = av;
            Bs[kk][r] = bv;
        }
        __syncthreads();
#pragma unroll
        for (int kk = 0; kk < KT; kk++) {
            float4 av = *reinterpret_cast<const float4*>(&As[kk][ty * 4]);
            float4 bv = *reinterpret_cast<const float4*>(&Bs[kk][tx * 4]);
            float a[4] = {av.x, av.y, av.z, av.w};
            float bb[4] = {bv.x, bv.y, bv.z, bv.w};
#pragma unroll
            for (int ii = 0; ii < 4; ii++)
#pragma unroll
                for (int jj = 0; jj < 4; jj++) acc[ii][jj] += a[ii] * bb[jj];
        }
        __syncthreads();
    }

    int jb = j0 + tx * 4;
    float xj0 = xxb[jb], xj1 = xxb[jb + 1], xj2 = xxb[jb + 2], xj3 = xxb[jb + 3];
#pragma unroll
    for (int ii = 0; ii < 4; ii++) {
        int i = i0 + ty * 4 + ii;
        float xi = xxb[i];
        float4 o;
        o.x = 2.f * acc[ii][0] - xi - xj0;
        o.y = 2.f * acc[ii][1] - xi - xj1;
        o.z = 2.f * acc[ii][2] - xi - xj2;
        o.w = 2.f * acc[ii][3] - xi - xj3;
        *reinterpret_cast<float4*>(&Db[(size_t)i * NPTS + jb]) = o;
    }
}

// ---------------- top-K per row (iterative argmax) -------------------------
__global__ __launch_bounds__(256)
void topk_kernel(const float* __restrict__ dist, int* __restrict__ idx) {
    __shared__ float s[NPTS];
    __shared__ float bv[256];
    __shared__ int   bi[256];
    int b = blockIdx.y, i = blockIdx.x;
    const float* row = dist + ((size_t)b * NPTS + i) * NPTS;
    int tid = threadIdx.x;
    for (int j = tid; j < NPTS; j += 256) s[j] = row[j];
    __syncthreads();
    for (int k = 0; k < KNN; k++) {
        float best = -1e30f; int bidx = NPTS;
        for (int j = tid; j < NPTS; j += 256) {
            float v = s[j];
            if (v > best) { best = v; bidx = j; }
        }
        bv[tid] = best; bi[tid] = bidx;
        __syncthreads();
        for (int st = 128; st > 0; st >>= 1) {
            if (tid < st) {
                float v2 = bv[tid + st]; int i2 = bi[tid + st];
                if (v2 > bv[tid] || (v2 == bv[tid] && i2 < bi[tid])) {
                    bv[tid] = v2; bi[tid] = i2;
                }
            }
            __syncthreads();
        }
        if (tid == 0) {
            idx[((size_t)b * NPTS + i) * KNN + k] = bi[0];
            s[bi[0]] = -1e30f;
        }
        __syncthreads();
    }
}

// ---------------- block 0 (coords, 9-ch edge feature with cross) ----------
__global__ void edge0_kernel(const float* __restrict__ x, const int* __restrict__ idx,
                             const float* __restrict__ W,  const float* __restrict__ gg,
                             const float* __restrict__ bb, const float* __restrict__ mm,
                             const float* __restrict__ vv, float* __restrict__ cat) {
    int p = blockIdx.x;
    int b = p / NPTS;
    __shared__ float nb[KNN][3];
    __shared__ float Ws[64 * 9];
    __shared__ float cc[3];
    int tid = threadIdx.x;  // 64 threads
    if (tid < 3) cc[tid] = x[(size_t)p * 3 + tid];
    if (tid < KNN) {
        int j = idx[(size_t)p * KNN + tid];
        const float* xr = x + ((size_t)b * NPTS + j) * 3;
        nb[tid][0] = xr[0]; nb[tid][1] = xr[1]; nb[tid][2] = xr[2];
    }
    for (int t = tid; t < 576; t += 64) Ws[t] = W[t];
    __syncthreads();

    int o = tid;
    const float* w = &Ws[o * 9];
    float c0 = cc[0], c1 = cc[1], c2 = cc[2];
    float wc = w[6] * c0 + w[7] * c1 + w[8] * c2;
    float best = -1e30f;
#pragma unroll
    for (int k = 0; k < KNN; k++) {
        float n0 = nb[k][0], n1 = nb[k][1], n2 = nb[k][2];
        float d = w[0] * (n0 - c0) + w[1] * (n1 - c1) + w[2] * (n2 - c2)
                + w[3] * (c1 * n2 - c2 * n1)
                + w[4] * (c2 * n0 - c0 * n2)
                + w[5] * (c0 * n1 - c1 * n0)
                + wc;
        best = fmaxf(best, d);
    }
    // BN scale > 0 and LeakyReLU monotone => max commutes
    float sc = gg[o] * rsqrtf(vv[o] + EPSBN);
    float y = sc * best + (bb[o] - mm[o] * sc);
    cat[(size_t)p * CATC + o] = (y >= 0.f) ? y : 0.2f * y;
}

// ---------------- weight delta Wc = Wb - Wa --------------------------------
__global__ void wc_kernel(const float* __restrict__ W, float* __restrict__ Wc,
                          int cout, int cin) {
    int t = blockIdx.x * blockDim.x + threadIdx.x;
    if (t >= cout * cin) return;
    int o = t / cin, c = t % cin;
    Wc[t] = W[(size_t)o * 2 * cin + cin + c] - W[(size_t)o * 2 * cin + c];
}

// ---------------- point-wise GEMM: Out[r,o] = X[r,:] . Wm[o,:] -------------
__global__ __launch_bounds__(256)
void gemm_xw_kernel(const float* __restrict__ X, int ldx,
                    const float* __restrict__ Wm, int ldw,
                    int C, int cout, float* __restrict__ Out) {
    __shared__ float As[KT][PAD];
    __shared__ float Bs[KT][PAD];
    int i0 = blockIdx.x * TI, j0 = blockIdx.y * TJ;
    int tid = threadIdx.x;
    int tx = tid & 15, ty = tid >> 4;

    float acc[4][4];
#pragma unroll
    for (int ii = 0; ii < 4; ii++)
#pragma unroll
        for (int jj = 0; jj < 4; jj++) acc[ii][jj] = 0.f;

    for (int k0 = 0; k0 < C; k0 += KT) {
        for (int t = tid; t < TI * KT; t += 256) {
            int r = t >> 4, kk = t & 15;
            float av = 0.f, bv = 0.f;
            if (k0 + kk < C) {
                av = X [(size_t)(i0 + r) * ldx + k0 + kk];
                bv = Wm[(size_t)(j0 + r) * ldw + k0 + kk];
            }
            As[kk][r] = av;
            Bs[kk][r] = bv;
        }
        __syncthreads();
#pragma unroll
        for (int kk = 0; kk < KT; kk++) {
            float4 av = *reinterpret_cast<const float4*>(&As[kk][ty * 4]);
            float4 bv = *reinterpret_cast<const float4*>(&Bs[kk][tx * 4]);
            float a[4] = {av.x, av.y, av.z, av.w};
            float bb[4] = {bv.x, bv.y, bv.z, bv.w};
#pragma unroll
            for (int ii = 0; ii < 4; ii++)
#pragma unroll
                for (int jj = 0; jj < 4; jj++) acc[ii][jj] += a[ii] * bb[jj];
        }
        __syncthreads();
    }
#pragma unroll
    for (int ii = 0; ii < 4; ii++) {
        int i = i0 + ty * 4 + ii;
        int j = j0 + tx * 4;
        float4 o = make_float4(acc[ii][0], acc[ii][1], acc[ii][2], acc[ii][3]);
        *reinterpret_cast<float4*>(&Out[(size_t)i * cout + j]) = o;
    }
}

// ---------------- gather-max + BN + LReLU (blocks 1..3) --------------------
__global__ void gathermax_kernel(const float* __restrict__ U, const float* __restrict__ V,
                                 const int* __restrict__ idx,
                                 const float* __restrict__ gg, const float* __restrict__ bb,
                                 const float* __restrict__ mm, const float* __restrict__ vv,
                                 int cout, int off, float* __restrict__ cat) {
    int p = blockIdx.x;
    int b = p / NPTS;
    __shared__ int sidx[KNN];
    if (threadIdx.x < KNN) sidx[threadIdx.x] = idx[(size_t)p * KNN + threadIdx.x];
    __syncthreads();
    for (int o = threadIdx.x; o < cout; o += blockDim.x) {
        float mx = -1e30f;
#pragma unroll 4
        for (int k = 0; k < KNN; k++)
            mx = fmaxf(mx, U[((size_t)b * NPTS + sidx[k]) * cout + o]);
        float pre = mx + V[(size_t)p * cout + o];
        float sc = gg[o] * rsqrtf(vv[o] + EPSBN);
        float y = sc * pre + (bb[o] - mm[o] * sc);
        cat[(size_t)p * CATC + off + o] = (y >= 0.f) ? y : 0.2f * y;
    }
}

// ---------------- layer 4: GEMM with max-over-N epilogue (partial) ---------
__global__ __launch_bounds__(256)
void conv4max_kernel(const float* __restrict__ cat, const float* __restrict__ W4,
                     float* __restrict__ Zp) {
    __shared__ float As[KT][PAD];
    __shared__ float Bs[KT][PAD];
    __shared__ float red[64][17];
    int b = blockIdx.z, seg = blockIdx.y;
    int o0 = blockIdx.x * 64;
    const float* catb = cat + (size_t)b * NPTS * CATC;
    int tid = threadIdx.x, tx = tid & 15, ty = tid >> 4;

    float rmax[4] = {-1e30f, -1e30f, -1e30f, -1e30f};

    for (int n0 = seg * 1024; n0 < seg * 1024 + 1024; n0 += 64) {
        float acc[4][4];
#pragma unroll
        for (int ii = 0; ii < 4; ii++)
#pragma unroll
            for (int jj = 0; jj < 4; jj++) acc[ii][jj] = 0.f;

        for (int k0 = 0; k0 < CATC; k0 += KT) {
            for (int t = tid; t < 64 * KT; t += 256) {
                int r = t >> 4, kk = t & 15;
                As[kk][r] = W4  [(size_t)(o0 + r) * CATC + k0 + kk];
                Bs[kk][r] = catb[(size_t)(n0 + r) * CATC + k0 + kk];
            }
            __syncthreads();
#pragma unroll
            for (int kk = 0; kk < KT; kk++) {
                float4 av = *reinterpret_cast<const float4*>(&As[kk][ty * 4]);
                float4 bv = *reinterpret_cast<const float4*>(&Bs[kk][tx * 4]);
                float a[4] = {av.x, av.y, av.z, av.w};
                float bb[4] = {bv.x, bv.y, bv.z, bv.w};
#pragma unroll
                for (int ii = 0; ii < 4; ii++)
#pragma unroll
                    for (int jj = 0; jj < 4; jj++) acc[ii][jj] += a[ii] * bb[jj];
            }
            __syncthreads();
        }
#pragma unroll
        for (int ii = 0; ii < 4; ii++)
#pragma unroll
            for (int jj = 0; jj < 4; jj++) rmax[ii] = fmaxf(rmax[ii], acc[ii][jj]);
    }
#pragma unroll
    for (int ii = 0; ii < 4; ii++) red[ty * 4 + ii][tx] = rmax[ii];
    __syncthreads();
    if (tid < 64) {
        float m = -1e30f;
#pragma unroll
        for (int t = 0; t < 16; t++) m = fmaxf(m, red[tid][t]);
        Zp[((size_t)b * 512 + o0 + tid) * 4 + seg] = m;
    }
}

// ---------------- final head: max segs + BN + LReLU + 2 linears ------------
__global__ void head_kernel(const float* __restrict__ Zp,
                            const float* __restrict__ g4, const float* __restrict__ b4,
                            const float* __restrict__ m4, const float* __restrict__ v4,
                            const float* __restrict__ We, const float* __restrict__ Wh,
                            const float* __restrict__ bh, float* __restrict__ out) {
    int b = blockIdx.x;
    int o = threadIdx.x;  // 512 threads
    __shared__ float h[512];
    __shared__ float emb[128];
    float m = -1e30f;
#pragma unroll
    for (int s = 0; s < 4; s++) m = fmaxf(m, Zp[((size_t)b * 512 + o) * 4 + s]);
    float sc = g4[o] * rsqrtf(v4[o] + EPSBN);
    float y = sc * m + (b4[o] - m4[o] * sc);
    h[o] = (y >= 0.f) ? y : 0.2f * y;
    __syncthreads();
    if (o < 128) {
        float s = 0.f;
        for (int c = 0; c < 512; c++) s += We[(size_t)o * 512 + c] * h[c];
        emb[o] = s;
    }
    __syncthreads();
    if (o < 128) {
        float s = bh[o];
        for (int c = 0; c < 128; c++) s += Wh[(size_t)o * 128 + c] * emb[c];
        out[(size_t)b * 128 + o] = s;
    }
}

// ---------------------------------------------------------------------------
extern "C" void kernel_launch(void* const* d_in, const int* in_sizes, int n_in,
                              void* d_out, int out_size) {
    const float* x = (const float*)d_in[0];
    const float *W[5], *G[5], *Bp[5], *M[5], *V[5];
    for (int l = 0; l < 5; l++) {
        W[l]  = (const float*)d_in[1 + 5 * l];
        G[l]  = (const float*)d_in[2 + 5 * l];
        Bp[l] = (const float*)d_in[3 + 5 * l];
        M[l]  = (const float*)d_in[4 + 5 * l];
        V[l]  = (const float*)d_in[5 + 5 * l];
    }
    const float* We = (const float*)d_in[26];
    const float* Wh = (const float*)d_in[27];
    const float* bh = (const float*)d_in[28];
    float* out = (float*)d_out;

    float *dist, *xxp, *cat, *Up, *Vp, *Wc, *Zp;
    int* idx;
    cudaGetSymbolAddress((void**)&dist, g_dist);
    cudaGetSymbolAddress((void**)&idx,  g_idx);
    cudaGetSymbolAddress((void**)&xxp,  g_xx);
    cudaGetSymbolAddress((void**)&cat,  g_cat);
    cudaGetSymbolAddress((void**)&Up,   g_U);
    cudaGetSymbolAddress((void**)&Vp,   g_V);
    cudaGetSymbolAddress((void**)&Wc,   g_Wc);
    cudaGetSymbolAddress((void**)&Zp,   g_Zp);

    const int M_ROWS = BATCH * NPTS;  // 16384

    // ---- block 0 (coords) ----
    xx_kernel<<<(M_ROWS + 255) / 256, 256>>>(x, 3, 3, xxp);
    gram_kernel<<<dim3(NPTS / TI, NPTS / TJ, BATCH), 256>>>(x, 3, 3, xxp, dist);
    topk_kernel<<<dim3(NPTS, BATCH), 256>>>(dist, idx);
    edge0_kernel<<<M_ROWS, 64>>>(x, idx, W[0], G[0], Bp[0], M[0], V[0], cat);

    // ---- blocks 1..3 ----
    struct { int cin, cout, off_in, off_out; } L[3] = {
        {64, 64, 0, 64}, {64, 128, 64, 128}, {128, 256, 128, 256}};
    for (int li = 0; li < 3; li++) {
        int l = li + 1;
        int cin = L[li].cin, cout = L[li].cout;
        const float* Xl = cat + L[li].off_in;

        xx_kernel<<<(M_ROWS + 255) / 256, 256>>>(Xl, CATC, cin, xxp);
        gram_kernel<<<dim3(NPTS / TI, NPTS / TJ, BATCH), 256>>>(Xl, CATC, cin, xxp, dist);
        topk_kernel<<<dim3(NPTS, BATCH), 256>>>(dist, idx);

        wc_kernel<<<(cout * cin + 255) / 256, 256>>>(W[l], Wc, cout, cin);
        gemm_xw_kernel<<<dim3(M_ROWS / TI, cout / TJ), 256>>>(Xl, CATC, W[l], 2 * cin,
                                                              cin, cout, Up);
        gemm_xw_kernel<<<dim3(M_ROWS / TI, cout / TJ), 256>>>(Xl, CATC, Wc, cin,
                                                              cin, cout, Vp);
        gathermax_kernel<<<M_ROWS, (cout < 256 ? cout : 256)>>>(
            Up, Vp, idx, G[l], Bp[l], M[l], V[l], cout, L[li].off_out, cat);
    }

    // ---- layer 4 + heads ----
    conv4max_kernel<<<dim3(8, 4, BATCH), 256>>>(cat, W[4], Zp);
    head_kernel<<<BATCH, 512>>>(Zp, G[4], Bp[4], M[4], V[4], We, Wh, bh, out);
}